// round 16
// baseline (speedup 1.0000x reference)
#include <cuda_runtime.h>

// CostVolume: out[b,c,h,w,d] = (w>=d) ? L[b,c,h,w] - R[b,c,h,w-d] : 0
// Shapes: B=4, C=32, H=128, W=240, D=24.  Rows = B*C*H = 16384.
// Pure HBM-store-bound: 377.5 MB out + 31.5 MB in.
// R15: 256-bit (v8) streaming stores + 2 rows per CTA.

#define W_DIM 240
#define D_DIM 24
#define ROWS_PER_CTA 2
#define NTHREADS 288
// float8 stores per CTA: 2 * 240 * 24 / 8 = 1440 = NTHREADS * 5
#define F8_PER_CTA ((ROWS_PER_CTA * W_DIM * D_DIM) / 8)
#define F8_PER_ROW ((W_DIM * D_DIM) / 8)   // 720

__global__ __launch_bounds__(NTHREADS)
void cost_volume_kernel(const float* __restrict__ left,
                        const float* __restrict__ right,
                        float* __restrict__ out)
{
    // Single smem block so a (clamped) small negative R index can never fault.
    __shared__ float S[2 * ROWS_PER_CTA * W_DIM];
    float* Ls = S;                               // [ROWS_PER_CTA * W_DIM]
    float* Rs = S + ROWS_PER_CTA * W_DIM;        // [ROWS_PER_CTA * W_DIM]

    const int t = threadIdx.x;
    const size_t row0 = (size_t)blockIdx.x * ROWS_PER_CTA;

    const float* lbase = left  + row0 * W_DIM;
    const float* rbase = right + row0 * W_DIM;

    #pragma unroll
    for (int i = t; i < ROWS_PER_CTA * W_DIM; i += NTHREADS) {
        Ls[i] = lbase[i];
        Rs[i] = rbase[i];
    }
    __syncthreads();

    float* obase = out + row0 * (size_t)(W_DIM * D_DIM);

    #pragma unroll
    for (int it = 0; it < F8_PER_CTA / NTHREADS; ++it) {
        const int idx = t + it * NTHREADS;        // 0..1439, consecutive across warp
        const int r   = idx / F8_PER_ROW;         // local row (0 or 1)
        const int rem = idx - r * F8_PER_ROW;     // 0..719
        const int w   = rem / 3;                  // output column
        const int q   = rem - w * 3;              // which float8 within D=24
        const int d0  = q * 8;

        const int  rb = r * W_DIM;
        const float lv = Ls[rb + w];
        const int  s0 = w - d0;

        float v[8];
        #pragma unroll
        for (int k = 0; k < 8; ++k) {
            const int sk = s0 - k;
            const float rv = Rs[rb + (sk < 0 ? 0 : sk)];  // clamped: always in-bounds
            v[k] = (sk >= 0) ? (lv - rv) : 0.0f;
        }

        // 256-bit streaming store (STG.E.256 on sm_100+): 32B per lane,
        // 1024B fully contiguous per warp instruction.
        float* addr = obase + (size_t)idx * 8;
        asm volatile(
            "st.global.cs.v8.f32 [%0], {%1,%2,%3,%4,%5,%6,%7,%8};"
            :: "l"(addr),
               "f"(v[0]), "f"(v[1]), "f"(v[2]), "f"(v[3]),
               "f"(v[4]), "f"(v[5]), "f"(v[6]), "f"(v[7])
            : "memory");
    }
}

extern "C" void kernel_launch(void* const* d_in, const int* in_sizes, int n_in,
                              void* d_out, int out_size)
{
    const float* left  = (const float*)d_in[0];
    const float* right = (const float*)d_in[1];
    float* out = (float*)d_out;

    const int rows = in_sizes[0] / W_DIM;        // B*C*H = 16384
    cost_volume_kernel<<<rows / ROWS_PER_CTA, NTHREADS>>>(left, right, out);
}